// round 14
// baseline (speedup 1.0000x reference)
#include <cuda_runtime.h>
#include <cuda_bf16.h>

// x (8,3,512,512) f32, y (8,3,1024,1024) f32, w1,b1,w2,b2 (3,) f32.
// out_lr = sigmoid(w2 * boxsum3x3_dil2(relu(w1*x+b1)) + b2) * relu(w1*x+b1)
// output = y + nearest_upsample_x2(out_lr)
//
// Champion shape (4 px/thread, 128 thr/block, 12288 blocks, shuffle halos,
// tanh-based sigmoid). Memory ops: 256-bit y LOADS (fewest L1 wavefronts on
// the read stream) + paired 128-bit STORES (smoother store drain across
// graph replays). All-default cache policy.

#define HH 512
#define WW 512
#define H2 1024
#define W2 1024
#define CC 3
#define FULL 0xFFFFFFFFu

__device__ __forceinline__ float actv(float v, float w1v, float b1v) {
    return fmaxf(fmaf(w1v, v, b1v), 0.0f);
}

// sigmoid(z) = 0.5 * tanh(0.5 z) + 0.5  (tanh.approx.f32 = single MUFU op)
__device__ __forceinline__ float fast_sigmoid(float z) {
    float t;
    asm("tanh.approx.f32 %0, %1;" : "=f"(t) : "f"(0.5f * z));
    return fmaf(0.5f, t, 0.5f);
}

// 256-bit global load, default cache policy (sm_100+)
__device__ __forceinline__ void ldg256(float* r, const float* p) {
    asm volatile("ld.global.v8.f32 {%0,%1,%2,%3,%4,%5,%6,%7}, [%8];"
                 : "=f"(r[0]), "=f"(r[1]), "=f"(r[2]), "=f"(r[3]),
                   "=f"(r[4]), "=f"(r[5]), "=f"(r[6]), "=f"(r[7])
                 : "l"(p));
}

__global__ __launch_bounds__(128, 16)
void fused_shift_gate_up_kernel(const float* __restrict__ x,
                                const float* __restrict__ y,
                                const float* __restrict__ w1,
                                const float* __restrict__ b1,
                                const float* __restrict__ w2,
                                const float* __restrict__ b2,
                                float* __restrict__ out)
{
    const int tid   = threadIdx.x;        // 0..127
    const int lane  = tid & 31;
    const int w0    = tid << 2;           // low-res column base (mult of 4)
    const int h     = blockIdx.y;         // low-res row
    const int plane = blockIdx.z;         // b*C + c
    const int c     = plane % CC;

    const float w1v = __ldg(w1 + c);
    const float b1v = __ldg(b1 + c);
    const float w2v = __ldg(w2 + c);
    const float b2v = __ldg(b2 + c);

    const unsigned r0 = (unsigned)plane * (H2 * W2)
                      + ((unsigned)h << 1) * W2 + ((unsigned)w0 << 1);
    const unsigned r1 = r0 + W2;
    const float* xc_p = x + (unsigned)plane * (HH * WW)
                          + (unsigned)h * WW + (unsigned)w0;

    float s0 = 0.f, s1 = 0.f, s2 = 0.f, s3 = 0.f;   // dilated box sums
    float xc0 = 0.f, xc1 = 0.f, xc2 = 0.f, xc3 = 0.f;

    const bool edgeL = (lane == 0);
    const bool edgeR = (lane == 31);
    const bool okL   = (w0 >= 2);
    const bool okR   = (w0 + 5 < WW);

    #pragma unroll
    for (int dr = 0; dr < 3; ++dr) {
        const int r = h + (dr - 1) * 2;   // warp-uniform
        if ((unsigned)r < (unsigned)HH) {
            const float* row = xc_p + (dr - 1) * 2 * WW;

            float4 Cv = *reinterpret_cast<const float4*>(row);
            float a0 = actv(Cv.x, w1v, b1v);
            float a1 = actv(Cv.y, w1v, b1v);
            float a2 = actv(Cv.z, w1v, b1v);
            float a3 = actv(Cv.w, w1v, b1v);

            // Halos from neighbor lanes (already activated)
            float aL2 = __shfl_up_sync(FULL, a2, 1);    // a[w0-2]
            float aL1 = __shfl_up_sync(FULL, a3, 1);    // a[w0-1]
            float aR0 = __shfl_down_sync(FULL, a0, 1);  // a[w0+4]
            float aR1 = __shfl_down_sync(FULL, a1, 1);  // a[w0+5]

            if (edgeL) {
                aL2 = 0.f; aL1 = 0.f;
                if (okL) {
                    float2 L = *reinterpret_cast<const float2*>(row - 2);
                    aL2 = actv(L.x, w1v, b1v);
                    aL1 = actv(L.y, w1v, b1v);
                }
            }
            if (edgeR) {
                aR0 = 0.f; aR1 = 0.f;
                if (okR) {
                    float2 R = *reinterpret_cast<const float2*>(row + 4);
                    aR0 = actv(R.x, w1v, b1v);
                    aR1 = actv(R.y, w1v, b1v);
                }
            }

            const float t02 = a0 + a2;
            const float t13 = a1 + a3;
            s0 += aL2 + t02;
            s1 += aL1 + t13;
            s2 += t02 + aR0;
            s3 += t13 + aR1;
            if (dr == 1) { xc0 = a0; xc1 = a1; xc2 = a2; xc3 = a3; }
        }
    }

    const float o0 = xc0 * fast_sigmoid(fmaf(w2v, s0, b2v));
    const float o1 = xc1 * fast_sigmoid(fmaf(w2v, s1, b2v));
    const float o2 = xc2 * fast_sigmoid(fmaf(w2v, s2, b2v));
    const float o3 = xc3 * fast_sigmoid(fmaf(w2v, s3, b2v));

    float ya[8], yb[8];
    ldg256(ya, y + r0);   // hi-res row 2h
    ldg256(yb, y + r1);   // hi-res row 2h+1

    // Paired 128-bit stores (smoother drain than 256-bit under replay overlap)
    float4 v;
    v = make_float4(ya[0] + o0, ya[1] + o0, ya[2] + o1, ya[3] + o1);
    *reinterpret_cast<float4*>(out + r0) = v;
    v = make_float4(ya[4] + o2, ya[5] + o2, ya[6] + o3, ya[7] + o3);
    *reinterpret_cast<float4*>(out + r0 + 4) = v;
    v = make_float4(yb[0] + o0, yb[1] + o0, yb[2] + o1, yb[3] + o1);
    *reinterpret_cast<float4*>(out + r1) = v;
    v = make_float4(yb[4] + o2, yb[5] + o2, yb[6] + o3, yb[7] + o3);
    *reinterpret_cast<float4*>(out + r1 + 4) = v;
}

extern "C" void kernel_launch(void* const* d_in, const int* in_sizes, int n_in,
                              void* d_out, int out_size)
{
    const float* x  = (const float*)d_in[0];
    const float* y  = (const float*)d_in[1];
    const float* w1 = (const float*)d_in[2];
    const float* b1 = (const float*)d_in[3];
    const float* w2 = (const float*)d_in[4];
    const float* b2 = (const float*)d_in[5];
    float* out = (float*)d_out;

    dim3 grid(1, HH, 8 * CC);   // one block per low-res row per plane
    dim3 block(128, 1, 1);      // 128 threads x 4 low-res cols = 512
    fused_shift_gate_up_kernel<<<grid, block>>>(x, y, w1, b1, w2, b2, out);
}

// round 15
// speedup vs baseline: 1.0555x; 1.0555x over previous
#include <cuda_runtime.h>
#include <cuda_bf16.h>

// x (8,3,512,512) f32, y (8,3,1024,1024) f32, w1,b1,w2,b2 (3,) f32.
// out_lr = sigmoid(w2 * boxsum3x3_dil2(relu(w1*x+b1)) + b2) * relu(w1*x+b1)
// output = y + nearest_upsample_x2(out_lr)
//
// CONVERGED CHAMPION (R6): 4 px/thread, 128 thr/block, 12288 blocks,
// warp-shuffle halos, single-MUFU tanh sigmoid, float4 .cs ld/st on y/out.
// Best replay-steady-state bench across 14 tested variants (36.9 us).

#define HH 512
#define WW 512
#define H2 1024
#define W2 1024
#define CC 3
#define FULL 0xFFFFFFFFu

__device__ __forceinline__ float actv(float v, float w1v, float b1v) {
    return fmaxf(fmaf(w1v, v, b1v), 0.0f);
}

// sigmoid(z) = 0.5 * tanh(0.5 z) + 0.5  (tanh.approx.f32 = single MUFU op)
__device__ __forceinline__ float fast_sigmoid(float z) {
    float t;
    asm("tanh.approx.f32 %0, %1;" : "=f"(t) : "f"(0.5f * z));
    return fmaf(0.5f, t, 0.5f);
}

__global__ __launch_bounds__(128, 16)
void fused_shift_gate_up_kernel(const float* __restrict__ x,
                                const float* __restrict__ y,
                                const float* __restrict__ w1,
                                const float* __restrict__ b1,
                                const float* __restrict__ w2,
                                const float* __restrict__ b2,
                                float* __restrict__ out)
{
    const int tid   = threadIdx.x;        // 0..127
    const int lane  = tid & 31;
    const int w0    = tid << 2;           // low-res column base (mult of 4)
    const int h     = blockIdx.y;         // low-res row
    const int plane = blockIdx.z;         // b*C + c
    const int c     = plane % CC;

    const float w1v = __ldg(w1 + c);
    const float b1v = __ldg(b1 + c);
    const float w2v = __ldg(w2 + c);
    const float b2v = __ldg(b2 + c);

    const float* xp = x + (size_t)plane * (HH * WW);

    float s0 = 0.f, s1 = 0.f, s2 = 0.f, s3 = 0.f;   // dilated box sums
    float xc0 = 0.f, xc1 = 0.f, xc2 = 0.f, xc3 = 0.f;

    const bool edgeL = (lane == 0);
    const bool edgeR = (lane == 31);
    const bool okL   = (w0 >= 2);
    const bool okR   = (w0 + 5 < WW);

    #pragma unroll
    for (int dr = 0; dr < 3; ++dr) {
        const int r = h + (dr - 1) * 2;   // warp-uniform
        if ((unsigned)r < (unsigned)HH) {
            const float* row = xp + (size_t)r * WW;

            float4 Cv = *reinterpret_cast<const float4*>(row + w0);
            float a0 = actv(Cv.x, w1v, b1v);
            float a1 = actv(Cv.y, w1v, b1v);
            float a2 = actv(Cv.z, w1v, b1v);
            float a3 = actv(Cv.w, w1v, b1v);

            // Halos from neighbor lanes (already activated)
            float aL2 = __shfl_up_sync(FULL, a2, 1);    // a[w0-2]
            float aL1 = __shfl_up_sync(FULL, a3, 1);    // a[w0-1]
            float aR0 = __shfl_down_sync(FULL, a0, 1);  // a[w0+4]
            float aR1 = __shfl_down_sync(FULL, a1, 1);  // a[w0+5]

            if (edgeL) {
                aL2 = 0.f; aL1 = 0.f;
                if (okL) {
                    float2 L = *reinterpret_cast<const float2*>(row + w0 - 2);
                    aL2 = actv(L.x, w1v, b1v);
                    aL1 = actv(L.y, w1v, b1v);
                }
            }
            if (edgeR) {
                aR0 = 0.f; aR1 = 0.f;
                if (okR) {
                    float2 R = *reinterpret_cast<const float2*>(row + w0 + 4);
                    aR0 = actv(R.x, w1v, b1v);
                    aR1 = actv(R.y, w1v, b1v);
                }
            }

            const float t02 = a0 + a2;
            const float t13 = a1 + a3;
            s0 += aL2 + t02;
            s1 += aL1 + t13;
            s2 += t02 + aR0;
            s3 += t13 + aR1;
            if (dr == 1) { xc0 = a0; xc1 = a1; xc2 = a2; xc3 = a3; }
        }
    }

    const float o0 = xc0 * fast_sigmoid(fmaf(w2v, s0, b2v));
    const float o1 = xc1 * fast_sigmoid(fmaf(w2v, s1, b2v));
    const float o2 = xc2 * fast_sigmoid(fmaf(w2v, s2, b2v));
    const float o3 = xc3 * fast_sigmoid(fmaf(w2v, s3, b2v));

    // High-res 2x8 patch: rows 2h, 2h+1; cols 2*w0 .. 2*w0+7 (16B aligned)
    const size_t obase = (size_t)plane * ((size_t)H2 * W2);
    const size_t r0 = obase + (size_t)(2 * h) * W2 + (size_t)(2 * w0);
    const size_t r1 = r0 + W2;

    float4 ya0 = __ldcs(reinterpret_cast<const float4*>(y + r0));
    float4 yb0 = __ldcs(reinterpret_cast<const float4*>(y + r0 + 4));
    float4 ya1 = __ldcs(reinterpret_cast<const float4*>(y + r1));
    float4 yb1 = __ldcs(reinterpret_cast<const float4*>(y + r1 + 4));

    float4 ua0 = make_float4(ya0.x + o0, ya0.y + o0, ya0.z + o1, ya0.w + o1);
    float4 ub0 = make_float4(yb0.x + o2, yb0.y + o2, yb0.z + o3, yb0.w + o3);
    float4 ua1 = make_float4(ya1.x + o0, ya1.y + o0, ya1.z + o1, ya1.w + o1);
    float4 ub1 = make_float4(yb1.x + o2, yb1.y + o2, yb1.z + o3, yb1.w + o3);

    __stcs(reinterpret_cast<float4*>(out + r0),     ua0);
    __stcs(reinterpret_cast<float4*>(out + r0 + 4), ub0);
    __stcs(reinterpret_cast<float4*>(out + r1),     ua1);
    __stcs(reinterpret_cast<float4*>(out + r1 + 4), ub1);
}

extern "C" void kernel_launch(void* const* d_in, const int* in_sizes, int n_in,
                              void* d_out, int out_size)
{
    const float* x  = (const float*)d_in[0];
    const float* y  = (const float*)d_in[1];
    const float* w1 = (const float*)d_in[2];
    const float* b1 = (const float*)d_in[3];
    const float* w2 = (const float*)d_in[4];
    const float* b2 = (const float*)d_in[5];
    float* out = (float*)d_out;

    dim3 grid(1, HH, 8 * CC);   // one block per low-res row per plane
    dim3 block(128, 1, 1);      // 128 threads x 4 low-res cols = 512
    fused_shift_gate_up_kernel<<<grid, block>>>(x, y, w1, b1, w2, b2, out);
}